// round 16
// baseline (speedup 1.0000x reference)
#include <cuda_runtime.h>
#include <cuda.h>
#include <cstdint>

// ----------------------------------------------------------------------------
// BasePatchOrthogonalMix as one GEMM: out[m,e] = sum_d patch[m,d] * W[e,d]
//   m = (b,hp,wp) = 65536,  d/e = (c,ph,pw) = 1024
//
// R15: FUSED gather+GEMM with NO per-element rounding on A.
//  * tcgen05 tf32 ignores low mantissa bits (truncation). With B pre-rounded
//    (rna), the A-truncation error term sum_k e_a(k)*b(k) has random sign
//    (sign of b) -> zero-mean, ~3.1e-4 relative. RSS with the base tf32
//    error (2.9e-4) ≈ 4.3e-4 < 1e-3 budget. So A needs no cvt at all.
//  * Producers (warps 0-7): cp.async.cg 16B gather of the A tile straight
//    from x into SW128-swizzled smem — 8 instrs/thread/iter (R14's 32 scalar
//    cvts made fused staging issue-bound: alu 24.9%, 3072 cyc/iter).
//  * B via TMA from rna-rounded g_Wr (pre_w, 4 MB, ~3 us — the only pre-pass).
//  * Consumer warp 8: tcgen05 tf32 SS MMAs (256x256xK32, TMEM 512 cols),
//    3-stage ring, commits free stages (proven R6 loop).
//  Fallback warp-mma kernel + numRegs dispatch retained.
// ----------------------------------------------------------------------------

#if defined(__CUDA_ARCH__) && (defined(__CUDA_ARCH_FEAT_SM103_ALL) || defined(__CUDA_ARCH_FEAT_SM100_ALL))
#define TCGEN05_OK 1
#else
#define TCGEN05_OK 0
#endif

__device__ float g_Wr[1024 * 1024];

// ======================== common helpers ====================================

__device__ __forceinline__ uint32_t f2tf32(float f) {
    uint32_t u;
    asm("cvt.rna.tf32.f32 %0, %1;" : "=r"(u) : "f"(f));
    return u;
}

__device__ __forceinline__ float4 cvt4(float4 v) {
    float4 t;
    t.x = __uint_as_float(f2tf32(v.x));
    t.y = __uint_as_float(f2tf32(v.y));
    t.z = __uint_as_float(f2tf32(v.z));
    t.w = __uint_as_float(f2tf32(v.w));
    return t;
}

__device__ __forceinline__ uint32_t smem_u32(const void* p) {
    uint32_t a;
    asm("{ .reg .u64 t; cvta.to.shared.u64 t, %1; cvt.u32.u64 %0, t; }" : "=r"(a) : "l"(p));
    return a;
}

// ======================== pre-pass: W rounding only =========================

__global__ void __launch_bounds__(256) pre_w(const float* __restrict__ w) {
    const int i = (blockIdx.x * 256 + threadIdx.x) * 4;
    *(float4*)(g_Wr + i) = cvt4(*(const float4*)(w + i));
}

// ======================== fused tcgen05 GEMM ================================

#define TC_THREADS     288                 // warps 0-7 producers, warp 8 MMA
#define TC_TILE_M      256
#define TC_TILE_N      256
#define TC_NKT         32
#define TC_STAGES      3
#define TC_A_BYTES     (TC_TILE_M * 128)   // 32768
#define TC_B_BYTES     (TC_TILE_N * 128)   // 32768
#define TC_STAGE_BYTES (TC_A_BYTES + TC_B_BYTES)          // 65536
#define TC_SMEM_CTRL   1024
#define TC_SMEM_BYTES  (TC_SMEM_CTRL + TC_STAGES * TC_STAGE_BYTES)   // 197632

// idesc kind::tf32: dtype=F32(1)<<4, atype=TF32(2)<<7, btype=TF32(2)<<10,
// n_dim=N>>3 at [17:23), m_dim=M>>4 at [24:29) (M=128 per MMA)
#define TC_IDESC  ((1u << 4) | (2u << 7) | (2u << 10) | ((TC_TILE_N / 8) << 17) | ((128 / 16) << 24))
// K-major SW128 desc base: layout=2<<61, version=1<<46, SBO=64<<32, LBO=1<<16
#define TC_DESC_BASE ((2ull << 61) | (1ull << 46) | (64ull << 32) | (1ull << 16))

#if TCGEN05_OK
__device__ __forceinline__ uint64_t make_desc(uint32_t addr) {
    return TC_DESC_BASE | ((uint64_t)(addr >> 4) & 0x3FFF);
}

__device__ __forceinline__ void mma_tf32_ss(uint32_t d_tmem, uint64_t ad, uint64_t bd,
                                            uint32_t en) {
    asm volatile(
        "{\n\t.reg .pred p;\n\tsetp.ne.u32 p, %4, 0;\n\t"
        "tcgen05.mma.cta_group::1.kind::tf32 [%0], %1, %2, %3, p;\n\t}"
        :: "r"(d_tmem), "l"(ad), "l"(bd), "r"(TC_IDESC), "r"(en) : "memory");
}

__device__ __forceinline__ void mbar_init(uint32_t a, uint32_t cnt) {
    asm volatile("mbarrier.init.shared.b64 [%0], %1;" :: "r"(a), "r"(cnt) : "memory");
}

__device__ __forceinline__ void mbar_wait(uint32_t a, uint32_t parity) {
    uint32_t done;
    asm volatile(
        "{\n\t.reg .pred p;\n\t"
        "mbarrier.try_wait.parity.acquire.cta.shared::cta.b64 p, [%1], %2;\n\t"
        "selp.b32 %0, 1, 0, p;\n\t}"
        : "=r"(done) : "r"(a), "r"(parity) : "memory");
    if (!done) {
        asm volatile(
            "{\n\t.reg .pred P1;\n\t"
            "WL_%=:\n\t"
            "mbarrier.try_wait.parity.acquire.cta.shared::cta.b64 P1, [%0], %1, 0x989680;\n\t"
            "@P1 bra.uni WD_%=;\n\t"
            "bra.uni WL_%=;\n\t"
            "WD_%=:\n\t}"
            :: "r"(a), "r"(parity) : "memory");
    }
}

__device__ __forceinline__ void tma2d(uint32_t smem_addr, const void* tmap,
                                      int cx, int cy, uint32_t mbar) {
    asm volatile(
        "cp.async.bulk.tensor.2d.shared::cta.global.tile.mbarrier::complete_tx::bytes "
        "[%0], [%1, {%2, %3}], [%4];"
        :: "r"(smem_addr), "l"(tmap), "r"(cx), "r"(cy), "r"(mbar) : "memory");
}
#endif  // TCGEN05_OK

__global__ void __launch_bounds__(TC_THREADS, 1)
patch_mix_tc(const float* __restrict__ x,
             const __grid_constant__ CUtensorMap tmB,
             float* __restrict__ y)
{
#if TCGEN05_OK
    extern __shared__ char smem[];
    const uint32_t smem_base = smem_u32(smem);
    const int tid  = threadIdx.x;
    const int warp = tid >> 5;
    const int lane = tid & 31;
    const int bN   = blockIdx.x;   // 0..3
    const int bM   = blockIdx.y;   // 0..255

    // ctrl: [0] tmem ptr; mbarriers: full[s]=64+16s, empty[s]=72+16s, done=160
    const uint32_t mb_full0  = smem_base + 64;
    const uint32_t mb_empty0 = smem_base + 72;
    const uint32_t mb_done   = smem_base + 160;

    if (warp == 0) {
        asm volatile("tcgen05.alloc.cta_group::1.sync.aligned.shared::cta.b32 [%0], %1;"
                     :: "r"(smem_base), "r"(512u) : "memory");
    }
    if (tid == 0) {
#pragma unroll
        for (int s = 0; s < TC_STAGES; ++s) {
            mbar_init(mb_full0 + 16 * s, 257);  // 256 producer arrives + expect_tx
            mbar_init(mb_empty0 + 16 * s, 1);   // 1 tcgen05 commit
        }
        mbar_init(mb_done, 1);
    }
    __syncthreads();
    uint32_t tmem;
    asm volatile("ld.shared.b32 %0, [%1];" : "=r"(tmem) : "r"(smem_base));

    uint32_t Aaddr[TC_STAGES], Baddr[TC_STAGES];
#pragma unroll
    for (int s = 0; s < TC_STAGES; ++s) {
        Aaddr[s] = smem_base + TC_SMEM_CTRL + s * TC_STAGE_BYTES;
        Baddr[s] = Aaddr[s] + TC_A_BYTES;
    }

    if (warp < 8) {
        // ======= producers: stage A row tid via cp.async.cg (no rounding) ===
        const int r   = tid;                 // A row within tile (0..255)
        const int m_g = bM * TC_TILE_M + r;
        const int bb  = m_g >> 12;
        const int hp  = (m_g >> 6) & 63;
        const int wp  = m_g & 63;
        const float* pA = x + (((size_t)bb) << 22) + (hp << 10) + wp * 4;

        const float* base[8];
#pragma unroll
        for (int k4 = 0; k4 < 8; ++k4)
            base[k4] = pA + (((size_t)(k4 >> 2)) << 16) + ((k4 & 3) << 8);
        const size_t kstride = (size_t)2 << 16;   // 2 channels per K tile

        uint32_t s8[8];
#pragma unroll
        for (int k4 = 0; k4 < 8; ++k4) {
            uint32_t bo = (uint32_t)r * 128 + k4 * 16;
            s8[k4] = bo ^ ((bo >> 3) & 0x70);     // SW128 swizzle
        }

        for (int kt = 0; kt < TC_NKT; ++kt) {
            const int s = kt % TC_STAGES;
            if (kt >= TC_STAGES)
                mbar_wait(mb_empty0 + 16 * s, ((kt / TC_STAGES) - 1) & 1);
            const uint32_t full = mb_full0 + 16 * s;
            if (tid == 0) {   // B tile via TMA; expect_tx counts as 1 arrive
                asm volatile("mbarrier.arrive.expect_tx.shared.b64 _, [%0], %1;"
                             :: "r"(full), "r"((uint32_t)TC_B_BYTES) : "memory");
                tma2d(Baddr[s], (const void*)&tmB, kt * 32, bN * TC_TILE_N, full);
            }
            const uint32_t As = Aaddr[s];
            const size_t ko = (size_t)kt * kstride;
#pragma unroll
            for (int k4 = 0; k4 < 8; ++k4) {
                asm volatile("cp.async.cg.shared.global [%0], [%1], 16;"
                             :: "r"(As + s8[k4]), "l"(base[k4] + ko) : "memory");
            }
            asm volatile("cp.async.commit_group;" ::: "memory");
            asm volatile("cp.async.wait_group 0;" ::: "memory");
            asm volatile("fence.proxy.async.shared::cta;" ::: "memory");
            asm volatile("mbarrier.arrive.shared.b64 _, [%0];" :: "r"(full) : "memory");
        }
    } else if (lane == 0) {
        // ==================== consumer: MMA issue + commits =================
        for (int kt = 0; kt < TC_NKT; ++kt) {
            const int s = kt % TC_STAGES;
            mbar_wait(mb_full0 + 16 * s, (kt / TC_STAGES) & 1);
            asm volatile("tcgen05.fence::after_thread_sync;" ::: "memory");
            const uint64_t aD = make_desc(Aaddr[s]);
            const uint64_t bD = make_desc(Baddr[s]);
#pragma unroll
            for (int h = 0; h < 2; ++h) {
#pragma unroll
                for (int ks = 0; ks < 4; ++ks) {
                    mma_tf32_ss(tmem + h * 256,
                                aD + h * 1024 + ks * 2,   // +128 rows = +1024 units
                                bD + ks * 2,
                                (kt > 0 || ks > 0) ? 1u : 0u);
                }
            }
            asm volatile(
                "tcgen05.commit.cta_group::1.mbarrier::arrive::one.shared::cluster.b64 [%0];"
                :: "r"(mb_empty0 + 16 * s) : "memory");
            if (kt == TC_NKT - 1) {
                asm volatile(
                    "tcgen05.commit.cta_group::1.mbarrier::arrive::one.shared::cluster.b64 [%0];"
                    :: "r"(mb_done) : "memory");
            }
        }
    }

    // -------- all threads: wait for final MMA completion
    mbar_wait(mb_done, 0);
    asm volatile("tcgen05.fence::after_thread_sync;" ::: "memory");

    // -------- epilogue: warps 0-7. h = M-half (warp>>2), p = partition (warp&3)
    if (warp < 8) {
        const int p = warp & 3;
        const int h = warp >> 2;
        const uint32_t tm = tmem + h * 256;
        const int mo = bM * TC_TILE_M + h * 128 + p * 32 + lane;
        const int ob  = mo >> 12;
        const int ohp = (mo >> 6) & 63;
        const int owp = mo & 63;
        float* yb = y + (((size_t)ob) << 22) + (ohp << 10) + owp * 4;

#pragma unroll
        for (int q = 0; q < 8; ++q) {
            uint32_t d[32];
            asm volatile(
                "tcgen05.ld.sync.aligned.32x32b.x32.b32 "
                "{%0,%1,%2,%3,%4,%5,%6,%7,%8,%9,%10,%11,%12,%13,%14,%15,"
                "%16,%17,%18,%19,%20,%21,%22,%23,%24,%25,%26,%27,%28,%29,%30,%31}, [%32];"
                : "=r"(d[0]), "=r"(d[1]), "=r"(d[2]), "=r"(d[3]), "=r"(d[4]), "=r"(d[5]),
                  "=r"(d[6]), "=r"(d[7]), "=r"(d[8]), "=r"(d[9]), "=r"(d[10]), "=r"(d[11]),
                  "=r"(d[12]), "=r"(d[13]), "=r"(d[14]), "=r"(d[15]), "=r"(d[16]), "=r"(d[17]),
                  "=r"(d[18]), "=r"(d[19]), "=r"(d[20]), "=r"(d[21]), "=r"(d[22]), "=r"(d[23]),
                  "=r"(d[24]), "=r"(d[25]), "=r"(d[26]), "=r"(d[27]), "=r"(d[28]), "=r"(d[29]),
                  "=r"(d[30]), "=r"(d[31])
                : "r"(tm + q * 32));
            asm volatile("tcgen05.wait::ld.sync.aligned;" ::: "memory");

            const int ebase = bN * TC_TILE_N + q * 32;
#pragma unroll
            for (int c4 = 0; c4 < 2; ++c4) {
                const int ce = (ebase >> 4) + c4;
#pragma unroll
                for (int ph = 0; ph < 4; ++ph) {
                    float4 o;
                    o.x = __uint_as_float(d[c4 * 16 + ph * 4 + 0]);
                    o.y = __uint_as_float(d[c4 * 16 + ph * 4 + 1]);
                    o.z = __uint_as_float(d[c4 * 16 + ph * 4 + 2]);
                    o.w = __uint_as_float(d[c4 * 16 + ph * 4 + 3]);
                    *(float4*)(yb + (((size_t)ce) << 16) + (ph << 8)) = o;
                }
            }
        }
    }

    asm volatile("tcgen05.fence::before_thread_sync;" ::: "memory");
    __syncthreads();
    if (warp == 0) {
        asm volatile("tcgen05.relinquish_alloc_permit.cta_group::1.sync.aligned;");
        asm volatile("tcgen05.dealloc.cta_group::1.sync.aligned.b32 %0, %1;"
                     :: "r"(tmem), "r"(512u));
    }
#else
    (void)x; (void)tmB; (void)y;
#endif
}

// ======================== fallback: proven R1 warp-mma ======================

#define FB_THREADS 256
#define FB_PADK    36
#define FB_ABUF    (128 * FB_PADK)
#define FB_SMEM_BYTES (4 * FB_ABUF * 4)

__device__ __forceinline__ void fb_mma(float d[4], const uint32_t a[4], const uint32_t b[2]) {
    asm volatile(
        "mma.sync.aligned.m16n8k8.row.col.f32.tf32.tf32.f32 "
        "{%0,%1,%2,%3}, {%4,%5,%6,%7}, {%8,%9}, {%0,%1,%2,%3};\n"
        : "+f"(d[0]), "+f"(d[1]), "+f"(d[2]), "+f"(d[3])
        : "r"(a[0]), "r"(a[1]), "r"(a[2]), "r"(a[3]),
          "r"(b[0]), "r"(b[1]));
}

__global__ void __launch_bounds__(FB_THREADS)
patch_mix_fb(const float* __restrict__ x,
             const float* __restrict__ Wm,
             float*       __restrict__ y)
{
    extern __shared__ float smemf[];
    float* As = smemf;
    float* Bs = smemf + 2 * FB_ABUF;

    const int tid  = threadIdx.x;
    const int bN   = blockIdx.x;
    const int bM   = blockIdx.y;

    const int lane = tid & 31;
    const int warp = tid >> 5;
    const int gid  = lane >> 2;
    const int tig  = lane & 3;
    const int wMo  = (warp >> 2) * 64;
    const int wNo  = (warp & 3) * 32;

    const int mA   = tid & 127;
    const int hsel = tid >> 7;

    const int m_g = bM * 128 + mA;
    const int bb  = m_g >> 12;
    const int hp  = (m_g >> 6) & 63;
    const int wp  = m_g & 63;

    const float* pA[4];
    const float* pB[4];
    int sAB[4];
#pragma unroll
    for (int l = 0; l < 4; ++l) {
        int k4   = 2 * l + hsel;
        int coff = k4 >> 2;
        int ph   = k4 & 3;
        pA[l] = x + (((size_t)(bb * 64 + coff)) << 16) + ((hp * 4 + ph) << 8) + wp * 4;
        pB[l] = Wm + (size_t)(bN * 128 + mA) * 1024 + k4 * 4;
        sAB[l] = mA * FB_PADK + k4 * 4;
    }

    float4 av[4], bv[4];
    float acc[4][4][4];
#pragma unroll
    for (int i = 0; i < 4; ++i)
#pragma unroll
        for (int j = 0; j < 4; ++j)
#pragma unroll
            for (int rr = 0; rr < 4; ++rr) acc[i][j][rr] = 0.0f;

#pragma unroll
    for (int l = 0; l < 4; ++l) {
        av[l] = *(const float4*)(pA[l]);
        bv[l] = *(const float4*)(pB[l]);
    }
#pragma unroll
    for (int l = 0; l < 4; ++l) {
        *(float4*)(As + sAB[l]) = cvt4(av[l]);
        *(float4*)(Bs + sAB[l]) = cvt4(bv[l]);
    }
    __syncthreads();

    for (int kt = 0; kt < 32; ++kt) {
        const int cur = kt & 1;
        if (kt < 31) {
#pragma unroll
            for (int l = 0; l < 4; ++l) {
                av[l] = *(const float4*)(pA[l] + (size_t)(kt + 1) * 131072);
                bv[l] = *(const float4*)(pB[l] + (kt + 1) * 32);
            }
        }
        const float* Ab = As + cur * FB_ABUF;
        const float* Bb = Bs + cur * FB_ABUF;
#pragma unroll
        for (int ks = 0; ks < 4; ++ks) {
            uint32_t af[4][4], bf[4][2];
            const int kc = ks * 8 + tig;
#pragma unroll
            for (int mt = 0; mt < 4; ++mt) {
                int rr = wMo + mt * 16 + gid;
                af[mt][0] = __float_as_uint(Ab[rr * FB_PADK + kc]);
                af[mt][1] = __float_as_uint(Ab[(rr + 8) * FB_PADK + kc]);
                af[mt][2] = __float_as_uint(Ab[rr * FB_PADK + kc + 4]);
                af[mt][3] = __float_as_uint(Ab[(rr + 8) * FB_PADK + kc + 4]);
            }
#pragma unroll
            for (int nt = 0; nt < 4; ++nt) {
                int rn = wNo + nt * 8 + gid;
                bf[nt][0] = __float_as_uint(Bb[rn * FB_PADK + kc]);
                bf[nt][1] = __float_as_uint(Bb[rn * FB_PADK + kc + 4]);
            }
#pragma unroll
            for (int mt = 0; mt < 4; ++mt)
#pragma unroll
                for (int nt = 0; nt < 4; ++nt)
                    fb_mma(acc[mt][nt], af[mt], bf[nt]);
        }
        if (kt < 31) {
            const int nxt = cur ^ 1;
#pragma unroll
            for (int l = 0; l < 4; ++l) {
                *(float4*)(As + nxt * FB_ABUF + sAB[l]) = cvt4(av[l]);
                *(float4*)(Bs + nxt * FB_ABUF + sAB[l]) = cvt4(bv[l]);
            }
            __syncthreads();
        }
    }

#pragma unroll
    for (int mt = 0; mt < 4; ++mt) {
#pragma unroll
        for (int h = 0; h < 2; ++h) {
            int m_out = bM * 128 + wMo + mt * 16 + gid + h * 8;
            int ob  = m_out >> 12;
            int ohp = (m_out >> 6) & 63;
            int owp = m_out & 63;
            float* ybase = y + (((size_t)ob) << 22) + (ohp << 10) + owp * 4;
#pragma unroll
            for (int nt = 0; nt < 4; ++nt) {
                int e   = bN * 128 + wNo + nt * 8 + 2 * tig;
                int ce  = e >> 4;
                int oph = (e >> 2) & 3;
                int opw = e & 3;
                float2 vv;
                vv.x = acc[mt][nt][h * 2];
                vv.y = acc[mt][nt][h * 2 + 1];
                *(float2*)(ybase + (ce << 16) + (oph << 8) + opw) = vv;
            }
        }
    }
}

// ======================== dispatch ==========================================

typedef CUresult (*EncodeTiledFn)(
    CUtensorMap*, CUtensorMapDataType, cuuint32_t, void*,
    const cuuint64_t*, const cuuint64_t*, const cuuint32_t*, const cuuint32_t*,
    CUtensorMapInterleave, CUtensorMapSwizzle, CUtensorMapL2promotion,
    CUtensorMapFloatOOBfill);

extern "C" void kernel_launch(void* const* d_in, const int* in_sizes, int n_in,
                              void* d_out, int out_size)
{
    const float* x  = (const float*)d_in[0];
    const float* Wm = (const float*)d_in[1];
    float*       y  = (float*)d_out;

    cudaFuncAttributes attr{};
    bool use_tc = false;
    if (cudaFuncGetAttributes(&attr, (const void*)patch_mix_tc) == cudaSuccess)
        use_tc = (attr.numRegs >= 40);

    EncodeTiledFn encode = nullptr;
    void* wr = nullptr;
    if (use_tc) {
        cudaDriverEntryPointQueryResult st;
        void* fn = nullptr;
        if (cudaGetDriverEntryPoint("cuTensorMapEncodeTiled", &fn,
                                    cudaEnableDefault, &st) == cudaSuccess &&
            st == cudaDriverEntryPointSuccess)
            encode = (EncodeTiledFn)fn;
        if (!encode || cudaGetSymbolAddress(&wr, g_Wr) != cudaSuccess)
            use_tc = false;
    }

    CUtensorMap tmB{};
    if (use_tc) {
        cuuint64_t dimsB[2]   = {1024, 1024};
        cuuint64_t strideB[1] = {1024 * 4};
        cuuint32_t boxB[2]    = {32, 256};
        cuuint32_t es[2]      = {1, 1};
        if (encode(&tmB, CU_TENSOR_MAP_DATA_TYPE_FLOAT32, 2, wr, dimsB, strideB,
                   boxB, es, CU_TENSOR_MAP_INTERLEAVE_NONE, CU_TENSOR_MAP_SWIZZLE_128B,
                   CU_TENSOR_MAP_L2_PROMOTION_L2_128B,
                   CU_TENSOR_MAP_FLOAT_OOB_FILL_NONE) != CUDA_SUCCESS)
            use_tc = false;
    }

    if (use_tc) {
        cudaFuncSetAttribute(patch_mix_tc,
                             cudaFuncAttributeMaxDynamicSharedMemorySize, TC_SMEM_BYTES);
        pre_w<<<1024, 256>>>(Wm);
        dim3 grid(4, 256);       // N inner: 4 CTAs per bM row share x in L2
        patch_mix_tc<<<grid, TC_THREADS, TC_SMEM_BYTES>>>(x, tmB, y);
    } else {
        cudaFuncSetAttribute(patch_mix_fb,
                             cudaFuncAttributeMaxDynamicSharedMemorySize, FB_SMEM_BYTES);
        dim3 grid(8, 512);
        patch_mix_fb<<<grid, FB_THREADS, FB_SMEM_BYTES>>>(x, Wm, y);
    }
}

// round 17
// speedup vs baseline: 1.8427x; 1.8427x over previous
#include <cuda_runtime.h>
#include <cuda.h>
#include <cstdint>

// ----------------------------------------------------------------------------
// BasePatchOrthogonalMix as one GEMM: out[m,e] = sum_d patch[m,d] * W[e,d]
//   m = (b,hp,wp) = 65536,  d/e = (c,ph,pw) = 1024
//
// R16: FULL-TMA fused gather+GEMM (enabled by R15's validated result that A
// needs NO rounding: tf32-truncation error on A is zero-mean when B is
// rna-rounded; measured rel_err 4.66e-4 < 1e-3).
//  * A: 8 TMA box loads per K-tile directly from x, viewed as 4D
//    [w:256][ph:4][hp:64][b*64+c:1024], box [256,1,4,1]. Each load lands as a
//    dense 4KB plane whose image is addr = m*16B -> 8-row core matrices are
//    dense 128B blocks. MMA consumes it via a general K-major descriptor:
//    LBO=256 (4KB, k-chunk->next plane), SBO=8 (128B, next 8 m-rows),
//    no swizzle. ks step = 2 planes = 512 units; M-half = 128 units.
//  * B: TMA from rna-rounded g_Wr (pre_w, 4MB, only pre-pass).
//  * Mainloop = R6 shape: 1 producer thread + 1 consumer thread, 3-stage
//    ring, tcgen05 commits free stages. No LDG/cvt/STS/wait_group anywhere.
//  Fallback warp-mma kernel + numRegs dispatch retained.
// ----------------------------------------------------------------------------

#if defined(__CUDA_ARCH__) && (defined(__CUDA_ARCH_FEAT_SM103_ALL) || defined(__CUDA_ARCH_FEAT_SM100_ALL))
#define TCGEN05_OK 1
#else
#define TCGEN05_OK 0
#endif

__device__ float g_Wr[1024 * 1024];

// ======================== common helpers ====================================

__device__ __forceinline__ uint32_t f2tf32(float f) {
    uint32_t u;
    asm("cvt.rna.tf32.f32 %0, %1;" : "=r"(u) : "f"(f));
    return u;
}

__device__ __forceinline__ float4 cvt4(float4 v) {
    float4 t;
    t.x = __uint_as_float(f2tf32(v.x));
    t.y = __uint_as_float(f2tf32(v.y));
    t.z = __uint_as_float(f2tf32(v.z));
    t.w = __uint_as_float(f2tf32(v.w));
    return t;
}

__device__ __forceinline__ uint32_t smem_u32(const void* p) {
    uint32_t a;
    asm("{ .reg .u64 t; cvta.to.shared.u64 t, %1; cvt.u32.u64 %0, t; }" : "=r"(a) : "l"(p));
    return a;
}

// ======================== pre-pass: W rounding only =========================

__global__ void __launch_bounds__(256) pre_w(const float* __restrict__ w) {
    const int i = (blockIdx.x * 256 + threadIdx.x) * 4;
    *(float4*)(g_Wr + i) = cvt4(*(const float4*)(w + i));
}

// ======================== fused full-TMA tcgen05 GEMM =======================

#define TC_THREADS     256
#define TC_TILE_M      256
#define TC_TILE_N      256
#define TC_NKT         32
#define TC_STAGES      3
#define TC_A_BYTES     (TC_TILE_M * 128)   // 32768: 8 planes x 4096 B
#define TC_B_BYTES     (TC_TILE_N * 128)   // 32768
#define TC_STAGE_BYTES (TC_A_BYTES + TC_B_BYTES)          // 65536
#define TC_SMEM_CTRL   1024
#define TC_SMEM_BYTES  (TC_SMEM_CTRL + TC_STAGES * TC_STAGE_BYTES)   // 197632

// idesc kind::tf32: dtype=F32(1)<<4, atype=TF32(2)<<7, btype=TF32(2)<<10,
// n_dim=N>>3 at [17:23), m_dim=M>>4 at [24:29) (M=128 per MMA)
#define TC_IDESC  ((1u << 4) | (2u << 7) | (2u << 10) | ((TC_TILE_N / 8) << 17) | ((128 / 16) << 24))
// B: canonical K-major SW128 desc (TMA-written, 128B rows)
#define TC_DESC_B_BASE ((2ull << 61) | (1ull << 46) | (64ull << 32) | (1ull << 16))
// A: general no-swizzle K-major desc. LBO=256 (4096B plane hop in k),
// SBO=8 (128B hop per 8 m-rows), version=1.
#define TC_DESC_A_BASE ((0ull << 61) | (1ull << 46) | (8ull << 32) | (256ull << 16))

#if TCGEN05_OK
__device__ __forceinline__ uint64_t make_desc_b(uint32_t addr) {
    return TC_DESC_B_BASE | ((uint64_t)(addr >> 4) & 0x3FFF);
}

__device__ __forceinline__ uint64_t make_desc_a(uint32_t addr) {
    return TC_DESC_A_BASE | ((uint64_t)(addr >> 4) & 0x3FFF);
}

__device__ __forceinline__ void mma_tf32_ss(uint32_t d_tmem, uint64_t ad, uint64_t bd,
                                            uint32_t en) {
    asm volatile(
        "{\n\t.reg .pred p;\n\tsetp.ne.u32 p, %4, 0;\n\t"
        "tcgen05.mma.cta_group::1.kind::tf32 [%0], %1, %2, %3, p;\n\t}"
        :: "r"(d_tmem), "l"(ad), "l"(bd), "r"(TC_IDESC), "r"(en) : "memory");
}

__device__ __forceinline__ void mbar_init(uint32_t a, uint32_t cnt) {
    asm volatile("mbarrier.init.shared.b64 [%0], %1;" :: "r"(a), "r"(cnt) : "memory");
}

__device__ __forceinline__ void mbar_wait(uint32_t a, uint32_t parity) {
    uint32_t done;
    asm volatile(
        "{\n\t.reg .pred p;\n\t"
        "mbarrier.try_wait.parity.acquire.cta.shared::cta.b64 p, [%1], %2;\n\t"
        "selp.b32 %0, 1, 0, p;\n\t}"
        : "=r"(done) : "r"(a), "r"(parity) : "memory");
    if (!done) {
        asm volatile(
            "{\n\t.reg .pred P1;\n\t"
            "WL_%=:\n\t"
            "mbarrier.try_wait.parity.acquire.cta.shared::cta.b64 P1, [%0], %1, 0x989680;\n\t"
            "@P1 bra.uni WD_%=;\n\t"
            "bra.uni WL_%=;\n\t"
            "WD_%=:\n\t}"
            :: "r"(a), "r"(parity) : "memory");
    }
}

__device__ __forceinline__ void tma2d(uint32_t smem_addr, const void* tmap,
                                      int cx, int cy, uint32_t mbar) {
    asm volatile(
        "cp.async.bulk.tensor.2d.shared::cta.global.tile.mbarrier::complete_tx::bytes "
        "[%0], [%1, {%2, %3}], [%4];"
        :: "r"(smem_addr), "l"(tmap), "r"(cx), "r"(cy), "r"(mbar) : "memory");
}

__device__ __forceinline__ void tma4d(uint32_t smem_addr, const void* tmap,
                                      int c0, int c1, int c2, int c3, uint32_t mbar) {
    asm volatile(
        "cp.async.bulk.tensor.4d.shared::cta.global.tile.mbarrier::complete_tx::bytes "
        "[%0], [%1, {%2, %3, %4, %5}], [%6];"
        :: "r"(smem_addr), "l"(tmap), "r"(c0), "r"(c1), "r"(c2), "r"(c3), "r"(mbar)
        : "memory");
}
#endif  // TCGEN05_OK

__global__ void __launch_bounds__(TC_THREADS, 1)
patch_mix_tc(const __grid_constant__ CUtensorMap tmA,
             const __grid_constant__ CUtensorMap tmB,
             float* __restrict__ y)
{
#if TCGEN05_OK
    extern __shared__ char smem[];
    const uint32_t smem_base = smem_u32(smem);
    const int tid  = threadIdx.x;
    const int warp = tid >> 5;
    const int lane = tid & 31;
    const int bN   = blockIdx.x;   // 0..3
    const int bM   = blockIdx.y;   // 0..255

    // ctrl: [0] tmem ptr; mbarriers: full[s]=64+16s, empty[s]=72+16s, done=160
    const uint32_t mb_full0  = smem_base + 64;
    const uint32_t mb_empty0 = smem_base + 72;
    const uint32_t mb_done   = smem_base + 160;

    if (warp == 0) {
        asm volatile("tcgen05.alloc.cta_group::1.sync.aligned.shared::cta.b32 [%0], %1;"
                     :: "r"(smem_base), "r"(512u) : "memory");
    }
    if (tid == 0) {
#pragma unroll
        for (int s = 0; s < TC_STAGES; ++s) {
            mbar_init(mb_full0 + 16 * s, 1);   // 1 expect_tx arrive
            mbar_init(mb_empty0 + 16 * s, 1);  // 1 tcgen05 commit
        }
        mbar_init(mb_done, 1);
    }
    __syncthreads();
    uint32_t tmem;
    asm volatile("ld.shared.b32 %0, [%1];" : "=r"(tmem) : "r"(smem_base));

    uint32_t Aaddr[TC_STAGES], Baddr[TC_STAGES];
#pragma unroll
    for (int s = 0; s < TC_STAGES; ++s) {
        Aaddr[s] = smem_base + TC_SMEM_CTRL + s * TC_STAGE_BYTES;
        Baddr[s] = Aaddr[s] + TC_A_BYTES;
    }

    if (warp == 0 && lane == 0) {
        // -------- producer: 8 A-plane TMAs + 1 B TMA per K-tile
        const int b   = bM >> 4;            // batch
        const int hp0 = (bM & 15) * 4;      // first patch-row of tile
        for (int kt = 0; kt < TC_NKT; ++kt) {
            const int s = kt % TC_STAGES;
            if (kt >= TC_STAGES)
                mbar_wait(mb_empty0 + 16 * s, ((kt / TC_STAGES) - 1) & 1);
            const uint32_t full = mb_full0 + 16 * s;
            asm volatile("mbarrier.arrive.expect_tx.shared.b64 _, [%0], %1;"
                         :: "r"(full), "r"((uint32_t)TC_STAGE_BYTES) : "memory");
#pragma unroll
            for (int j = 0; j < 8; ++j) {
                // plane j = (coff=j>>2, ph=j&3); channel c = kt*2 + coff
                tma4d(Aaddr[s] + j * 4096, (const void*)&tmA,
                      0, j & 3, hp0, b * 64 + kt * 2 + (j >> 2), full);
            }
            tma2d(Baddr[s], (const void*)&tmB, kt * 32, bN * TC_TILE_N, full);
        }
    }
    if (warp == 1 && lane == 0) {
        // -------- consumer: MMA issue + commits
        for (int kt = 0; kt < TC_NKT; ++kt) {
            const int s = kt % TC_STAGES;
            mbar_wait(mb_full0 + 16 * s, (kt / TC_STAGES) & 1);
            const uint64_t aD = make_desc_a(Aaddr[s]);
            const uint64_t bD = make_desc_b(Baddr[s]);
#pragma unroll
            for (int h = 0; h < 2; ++h) {
#pragma unroll
                for (int ks = 0; ks < 4; ++ks) {
                    // A: ks -> +2 planes = 512 units; h -> +128 rows = 128 units
                    mma_tf32_ss(tmem + h * 256,
                                aD + h * 128 + ks * 512,
                                bD + ks * 2,
                                (kt > 0 || ks > 0) ? 1u : 0u);
                }
            }
            asm volatile(
                "tcgen05.commit.cta_group::1.mbarrier::arrive::one.shared::cluster.b64 [%0];"
                :: "r"(mb_empty0 + 16 * s) : "memory");
            if (kt == TC_NKT - 1) {
                asm volatile(
                    "tcgen05.commit.cta_group::1.mbarrier::arrive::one.shared::cluster.b64 [%0];"
                    :: "r"(mb_done) : "memory");
            }
        }
    }

    // -------- all threads: wait for final MMA completion
    mbar_wait(mb_done, 0);
    asm volatile("tcgen05.fence::after_thread_sync;" ::: "memory");

    // -------- epilogue: 8 warps. h = M-half (warp>>2), p = partition (warp&3)
    {
        const int p = warp & 3;
        const int h = warp >> 2;
        const uint32_t tm = tmem + h * 256;
        const int mo = bM * TC_TILE_M + h * 128 + p * 32 + lane;
        const int ob  = mo >> 12;
        const int ohp = (mo >> 6) & 63;
        const int owp = mo & 63;
        float* yb = y + (((size_t)ob) << 22) + (ohp << 10) + owp * 4;

#pragma unroll
        for (int q = 0; q < 8; ++q) {
            uint32_t d[32];
            asm volatile(
                "tcgen05.ld.sync.aligned.32x32b.x32.b32 "
                "{%0,%1,%2,%3,%4,%5,%6,%7,%8,%9,%10,%11,%12,%13,%14,%15,"
                "%16,%17,%18,%19,%20,%21,%22,%23,%24,%25,%26,%27,%28,%29,%30,%31}, [%32];"
                : "=r"(d[0]), "=r"(d[1]), "=r"(d[2]), "=r"(d[3]), "=r"(d[4]), "=r"(d[5]),
                  "=r"(d[6]), "=r"(d[7]), "=r"(d[8]), "=r"(d[9]), "=r"(d[10]), "=r"(d[11]),
                  "=r"(d[12]), "=r"(d[13]), "=r"(d[14]), "=r"(d[15]), "=r"(d[16]), "=r"(d[17]),
                  "=r"(d[18]), "=r"(d[19]), "=r"(d[20]), "=r"(d[21]), "=r"(d[22]), "=r"(d[23]),
                  "=r"(d[24]), "=r"(d[25]), "=r"(d[26]), "=r"(d[27]), "=r"(d[28]), "=r"(d[29]),
                  "=r"(d[30]), "=r"(d[31])
                : "r"(tm + q * 32));
            asm volatile("tcgen05.wait::ld.sync.aligned;" ::: "memory");

            const int ebase = bN * TC_TILE_N + q * 32;
#pragma unroll
            for (int c4 = 0; c4 < 2; ++c4) {
                const int ce = (ebase >> 4) + c4;
#pragma unroll
                for (int ph = 0; ph < 4; ++ph) {
                    float4 o;
                    o.x = __uint_as_float(d[c4 * 16 + ph * 4 + 0]);
                    o.y = __uint_as_float(d[c4 * 16 + ph * 4 + 1]);
                    o.z = __uint_as_float(d[c4 * 16 + ph * 4 + 2]);
                    o.w = __uint_as_float(d[c4 * 16 + ph * 4 + 3]);
                    *(float4*)(yb + (((size_t)ce) << 16) + (ph << 8)) = o;
                }
            }
        }
    }

    asm volatile("tcgen05.fence::before_thread_sync;" ::: "memory");
    __syncthreads();
    if (warp == 0) {
        asm volatile("tcgen05.relinquish_alloc_permit.cta_group::1.sync.aligned;");
        asm volatile("tcgen05.dealloc.cta_group::1.sync.aligned.b32 %0, %1;"
                     :: "r"(tmem), "r"(512u));
    }
#else
    (void)tmA; (void)tmB; (void)y;
#endif
}

// ======================== fallback: proven R1 warp-mma ======================

#define FB_THREADS 256
#define FB_PADK    36
#define FB_ABUF    (128 * FB_PADK)
#define FB_SMEM_BYTES (4 * FB_ABUF * 4)

__device__ __forceinline__ void fb_mma(float d[4], const uint32_t a[4], const uint32_t b[2]) {
    asm volatile(
        "mma.sync.aligned.m16n8k8.row.col.f32.tf32.tf32.f32 "
        "{%0,%1,%2,%3}, {%4,%5,%6,%7}, {%8,%9}, {%0,%1,%2,%3};\n"
        : "+f"(d[0]), "+f"(d[1]), "+f"(d[2]), "+f"(d[3])
        : "r"(a[0]), "r"(a[1]), "r"(a[2]), "r"(a[3]),
          "r"(b[0]), "r"(b[1]));
}

__global__ void __launch_bounds__(FB_THREADS)
patch_mix_fb(const float* __restrict__ x,
             const float* __restrict__ Wm,
             float*       __restrict__ y)
{
    extern __shared__ float smemf[];
    float* As = smemf;
    float* Bs = smemf + 2 * FB_ABUF;

    const int tid  = threadIdx.x;
    const int bN   = blockIdx.x;
    const int bM   = blockIdx.y;

    const int lane = tid & 31;
    const int warp = tid >> 5;
    const int gid  = lane >> 2;
    const int tig  = lane & 3;
    const int wMo  = (warp >> 2) * 64;
    const int wNo  = (warp & 3) * 32;

    const int mA   = tid & 127;
    const int hsel = tid >> 7;

    const int m_g = bM * 128 + mA;
    const int bb  = m_g >> 12;
    const int hp  = (m_g >> 6) & 63;
    const int wp  = m_g & 63;

    const float* pA[4];
    const float* pB[4];
    int sAB[4];
#pragma unroll
    for (int l = 0; l < 4; ++l) {
        int k4   = 2 * l + hsel;
        int coff = k4 >> 2;
        int ph   = k4 & 3;
        pA[l] = x + (((size_t)(bb * 64 + coff)) << 16) + ((hp * 4 + ph) << 8) + wp * 4;
        pB[l] = Wm + (size_t)(bN * 128 + mA) * 1024 + k4 * 4;
        sAB[l] = mA * FB_PADK + k4 * 4;
    }

    float4 av[4], bv[4];
    float acc[4][4][4];
#pragma unroll
    for (int i = 0; i < 4; ++i)
#pragma unroll
        for (int j = 0; j < 4; ++j)
#pragma unroll
            for (int rr = 0; rr < 4; ++rr) acc[i][j][rr] = 0.0f;

#pragma unroll
    for (int l = 0; l < 4; ++l) {
        av[l] = *(const float4*)(pA[l]);
        bv[l] = *(const float4*)(pB[l]);
    }
#pragma unroll
    for (int l = 0; l < 4; ++l) {
        *(float4*)(As + sAB[l]) = cvt4(av[l]);
        *(float4*)(Bs + sAB[l]) = cvt4(bv[l]);
    }
    __syncthreads();

    for (int kt = 0; kt < 32; ++kt) {
        const int cur = kt & 1;
        if (kt < 31) {
#pragma unroll
            for (int l = 0; l < 4; ++l) {
                av[l] = *(const float4*)(pA[l] + (size_t)(kt + 1) * 131072);
                bv[l] = *(const float4*)(pB[l] + (kt + 1) * 32);
            }
        }
        const float* Ab = As + cur * FB_ABUF;
        const float* Bb = Bs + cur * FB_ABUF;
#pragma unroll
        for (int ks = 0; ks < 4; ++ks) {
            uint32_t af[4][4], bf[4][2];
            const int kc = ks * 8 + tig;
#pragma unroll
            for (int mt = 0; mt < 4; ++mt) {
                int rr = wMo + mt * 16 + gid;
                af[mt][0] = __float_as_uint(Ab[rr * FB_PADK + kc]);
                af[mt][1] = __float_as_uint(Ab[(rr + 8) * FB_PADK + kc]);
                af[mt][2] = __float_as_uint(Ab[rr * FB_PADK + kc + 4]);
                af[mt][3] = __float_as_uint(Ab[(rr + 8) * FB_PADK + kc + 4]);
            }
#pragma unroll
            for (int nt = 0; nt < 4; ++nt) {
                int rn = wNo + nt * 8 + gid;
                bf[nt][0] = __float_as_uint(Bb[rn * FB_PADK + kc]);
                bf[nt][1] = __float_as_uint(Bb[rn * FB_PADK + kc + 4]);
            }
#pragma unroll
            for (int mt = 0; mt < 4; ++mt)
#pragma unroll
                for (int nt = 0; nt < 4; ++nt)
                    fb_mma(acc[mt][nt], af[mt], bf[nt]);
        }
        if (kt < 31) {
            const int nxt = cur ^ 1;
#pragma unroll
            for (int l = 0; l < 4; ++l) {
                *(float4*)(As + nxt * FB_ABUF + sAB[l]) = cvt4(av[l]);
                *(float4*)(Bs + nxt * FB_ABUF + sAB[l]) = cvt4(bv[l]);
            }
            __syncthreads();
        }
    }

#pragma unroll
    for (int mt = 0; mt < 4; ++mt) {
#pragma unroll
        for (int h = 0; h < 2; ++h) {
            int m_out = bM * 128 + wMo + mt * 16 + gid + h * 8;
            int ob  = m_out >> 12;
            int ohp = (m_out >> 6) & 63;
            int owp = m_out & 63;
            float* ybase = y + (((size_t)ob) << 22) + (ohp << 10) + owp * 4;
#pragma unroll
            for (int nt = 0; nt < 4; ++nt) {
                int e   = bN * 128 + wNo + nt * 8 + 2 * tig;
                int ce  = e >> 4;
                int oph = (e >> 2) & 3;
                int opw = e & 3;
                float2 vv;
                vv.x = acc[mt][nt][h * 2];
                vv.y = acc[mt][nt][h * 2 + 1];
                *(float2*)(ybase + (ce << 16) + (oph << 8) + opw) = vv;
            }
        }
    }
}

// ======================== dispatch ==========================================

typedef CUresult (*EncodeTiledFn)(
    CUtensorMap*, CUtensorMapDataType, cuuint32_t, void*,
    const cuuint64_t*, const cuuint64_t*, const cuuint32_t*, const cuuint32_t*,
    CUtensorMapInterleave, CUtensorMapSwizzle, CUtensorMapL2promotion,
    CUtensorMapFloatOOBfill);

extern "C" void kernel_launch(void* const* d_in, const int* in_sizes, int n_in,
                              void* d_out, int out_size)
{
    const float* x  = (const float*)d_in[0];
    const float* Wm = (const float*)d_in[1];
    float*       y  = (float*)d_out;

    cudaFuncAttributes attr{};
    bool use_tc = false;
    if (cudaFuncGetAttributes(&attr, (const void*)patch_mix_tc) == cudaSuccess)
        use_tc = (attr.numRegs >= 40);

    EncodeTiledFn encode = nullptr;
    void* wr = nullptr;
    if (use_tc) {
        cudaDriverEntryPointQueryResult st;
        void* fn = nullptr;
        if (cudaGetDriverEntryPoint("cuTensorMapEncodeTiled", &fn,
                                    cudaEnableDefault, &st) == cudaSuccess &&
            st == cudaDriverEntryPointSuccess)
            encode = (EncodeTiledFn)fn;
        if (!encode || cudaGetSymbolAddress(&wr, g_Wr) != cudaSuccess)
            use_tc = false;
    }

    CUtensorMap tmA{}, tmB{};
    if (use_tc) {
        // A: x viewed as 4D [w:256][ph:4][hp:64][b*64+c:1024]
        cuuint64_t dimsA[4]    = {256, 4, 64, 1024};
        cuuint64_t strideA[3]  = {1024, 4096, 262144};   // bytes
        cuuint32_t boxA[4]     = {256, 1, 4, 1};
        cuuint32_t esA[4]      = {1, 1, 1, 1};
        cuuint64_t dimsB[2]    = {1024, 1024};
        cuuint64_t strideB[1]  = {1024 * 4};
        cuuint32_t boxB[2]     = {32, 256};
        cuuint32_t esB[2]      = {1, 1};
        if (encode(&tmA, CU_TENSOR_MAP_DATA_TYPE_FLOAT32, 4, (void*)x, dimsA, strideA,
                   boxA, esA, CU_TENSOR_MAP_INTERLEAVE_NONE, CU_TENSOR_MAP_SWIZZLE_NONE,
                   CU_TENSOR_MAP_L2_PROMOTION_L2_128B,
                   CU_TENSOR_MAP_FLOAT_OOB_FILL_NONE) != CUDA_SUCCESS)
            use_tc = false;
        else if (encode(&tmB, CU_TENSOR_MAP_DATA_TYPE_FLOAT32, 2, wr, dimsB, strideB,
                        boxB, esB, CU_TENSOR_MAP_INTERLEAVE_NONE, CU_TENSOR_MAP_SWIZZLE_128B,
                        CU_TENSOR_MAP_L2_PROMOTION_L2_128B,
                        CU_TENSOR_MAP_FLOAT_OOB_FILL_NONE) != CUDA_SUCCESS)
            use_tc = false;
    }

    if (use_tc) {
        cudaFuncSetAttribute(patch_mix_tc,
                             cudaFuncAttributeMaxDynamicSharedMemorySize, TC_SMEM_BYTES);
        pre_w<<<1024, 256>>>(Wm);
        dim3 grid(4, 256);       // N inner: 4 CTAs per bM row share x in L2
        patch_mix_tc<<<grid, TC_THREADS, TC_SMEM_BYTES>>>(tmA, tmB, y);
    } else {
        cudaFuncSetAttribute(patch_mix_fb,
                             cudaFuncAttributeMaxDynamicSharedMemorySize, FB_SMEM_BYTES);
        dim3 grid(8, 512);
        patch_mix_fb<<<grid, FB_THREADS, FB_SMEM_BYTES>>>(x, Wm, y);
    }
}